// round 6
// baseline (speedup 1.0000x reference)
#include <cuda_runtime.h>
#include <math.h>
#include <stdint.h>

// Problem constants
#define Bb 32
#define Gg 512
#define Cc 384
#define Hh 6
#define Vv 6
#define NN 513
#define HD 64
#define ROWS (Bb*NN)       // 16416
#define FROWS (Bb*Gg)      // 16384
#define NCLUST 2048
#define D2D 6272           // B*GRID*GRID
#define EPSv 1e-5f
#define C3 1152
#define C4 1536

// ---------------- scratch (device globals; no runtime allocation) ----------------
__device__ float g_qkv[ROWS*C3];
__device__ float g_att[ROWS*Cc];
__device__ float g_x1[ROWS*Cc];
__device__ float g_h[ROWS*C4];
__device__ float g_xffn[ROWS*Cc];
__device__ float g_adh[ROWS*16];
__device__ float g_x2[ROWS*Cc];
__device__ float g_feat[FROWS*Cc];
__device__ float g_rm[ROWS];
__device__ float g_rr[ROWS];
__device__ float g_rmF[FROWS];
__device__ float g_rrF[FROWS];
__device__ float g_segmax[NCLUST*Cc];
__device__ float g_segsum[NCLUST*Cc];
__device__ int   g_segcnt[NCLUST];
__device__ float g_bn3d[NCLUST*Cc];
__device__ float g_gmax[(size_t)Vv*D2D*Cc];
__device__ float g_gsum[(size_t)Vv*D2D*Cc];
__device__ int   g_gcnt[Vv*D2D];
__device__ float g_d2[(size_t)Vv*D2D*Cc];

// ---------------- device helpers ----------------
__device__ __forceinline__ float geluf(float x){
    return 0.5f*x*(1.0f + erff(x*0.7071067811865476f));
}

// Exact float atomic max via int/uint ordering trick (valid for IEEE-754, incl. -inf sentinel).
__device__ __forceinline__ void atomicMaxF(float* addr, float val){
    if (val >= 0.f) atomicMax((int*)addr, __float_as_int(val));
    else            atomicMin((unsigned int*)addr, (unsigned int)__float_as_int(val));
}

// Epilogue modes:
// 0: store C
// 1: gelu(C + bias[col])
// 2: add1 + ls[col]*(C + bias[col])                 (attention residual)
// 3: ls[col]*(C + bias[col])                        (ffn layerscale)
// 4: add1 + add2 + 0.5f*(C + bias[col])             (x2 combine)
// 5: mask[row]*(C + bias[col]) + add1               (view flatx, stored)
// 6: like 5 but no store: atomicMax/atomicAdd into segment pools
__device__ __forceinline__ float apply_epi(float v, int mode, int gr, size_t idx, int gc,
        const float* __restrict__ bias, const float* __restrict__ ls,
        const float* __restrict__ add1, const float* __restrict__ add2,
        const int* __restrict__ maski){
    switch(mode){
        case 1: return geluf(v + bias[gc]);
        case 2: return add1[idx] + ls[gc]*(v + bias[gc]);
        case 3: return ls[gc]*(v + bias[gc]);
        case 4: return add1[idx] + add2[idx] + 0.5f*(v + bias[gc]);
        case 5: case 6: return (float)maski[gr]*(v + bias[gc]) + add1[idx];
        default: return v;
    }
}

// ---------------- fused SGEMM: C = [LN](A)[MxK]*B[KxN] + epilogue ----------------
// Optional LN prologue on A: a' = (a - rmean[row])*rrstd[row]*lng[k] + lnb[k]
// Batched over blockIdx.z via strides. N % 128 == 0, K % 8 == 0 required.
#define TBM 128
#define TBN 128
#define TBK 8
__global__ __launch_bounds__(256) void k_sgemm_big(
        const float* __restrict__ A, const float* __restrict__ B,
        float* __restrict__ Cm, int M, int Nn, int K,
        int mode, const float* __restrict__ bias, const float* __restrict__ ls,
        const float* __restrict__ add1, const float* __restrict__ add2,
        const int* __restrict__ maski,
        const float* __restrict__ rmean, const float* __restrict__ rrstd,
        const float* __restrict__ lng, const float* __restrict__ lnb,
        long strideB, long strideC, int strideLn, int sBias, int sMask,
        const int* __restrict__ segidx, float* __restrict__ atomMax,
        float* __restrict__ atomSum, int nseg){
    int z = blockIdx.z;
    B  += (size_t)z*strideB;
    Cm += (size_t)z*strideC;
    if (lng){ lng += (size_t)z*strideLn; lnb += (size_t)z*strideLn; }
    if (bias) bias += (size_t)z*sBias;
    if (maski) maski += (size_t)z*sMask;
    if (segidx){
        segidx += (size_t)z*sMask;
        atomMax += (size_t)z*nseg*Nn;
        atomSum += (size_t)z*nseg*Nn;
    }

    __shared__ float As[2][TBK][TBM];
    __shared__ float Bs[2][TBK][TBN];
    int tid = threadIdx.x;
    int rowBase = blockIdx.y*TBM, colBase = blockIdx.x*TBN;
    int arow = tid >> 1;            // 0..127
    int acol = (tid & 1) * 4;       // 0 or 4
    int brow = tid >> 5;            // 0..7
    int bcol = (tid & 31) * 4;      // 0..124
    int tx = tid & 15, ty = tid >> 4;
    float acc[8][8] = {};
    bool aval = (rowBase + arow) < M;
    const float* Aptr = A + (size_t)(rowBase + arow)*K + acol;
    const float* Bptr = B + (size_t)brow*Nn + colBase + bcol;
    float rmv = 0.f, rrv = 0.f;
    bool doln = (lng != nullptr) && aval;
    if (doln){ rmv = rmean[rowBase + arow]; rrv = rrstd[rowBase + arow]; }

    float4 av = aval ? *(const float4*)(Aptr) : make_float4(0.f,0.f,0.f,0.f);
    if (doln){
        float4 gv = *(const float4*)(lng + acol);
        float4 bv4 = *(const float4*)(lnb + acol);
        av.x = (av.x - rmv)*rrv*gv.x + bv4.x;
        av.y = (av.y - rmv)*rrv*gv.y + bv4.y;
        av.z = (av.z - rmv)*rrv*gv.z + bv4.z;
        av.w = (av.w - rmv)*rrv*gv.w + bv4.w;
    }
    float4 bv = *(const float4*)(Bptr);
    int buf = 0;
    for (int k0 = 0; k0 < K; k0 += TBK){
        As[buf][acol+0][arow] = av.x; As[buf][acol+1][arow] = av.y;
        As[buf][acol+2][arow] = av.z; As[buf][acol+3][arow] = av.w;
        *(float4*)&Bs[buf][brow][bcol] = bv;
        __syncthreads();
        int kn = k0 + TBK;
        if (kn < K){
            av = aval ? *(const float4*)(Aptr + kn) : make_float4(0.f,0.f,0.f,0.f);
            if (doln){
                float4 gv = *(const float4*)(lng + kn + acol);
                float4 bv4 = *(const float4*)(lnb + kn + acol);
                av.x = (av.x - rmv)*rrv*gv.x + bv4.x;
                av.y = (av.y - rmv)*rrv*gv.y + bv4.y;
                av.z = (av.z - rmv)*rrv*gv.z + bv4.z;
                av.w = (av.w - rmv)*rrv*gv.w + bv4.w;
            }
            bv = *(const float4*)(Bptr + (size_t)kn*Nn);
        }
        #pragma unroll
        for (int kk = 0; kk < TBK; kk++){
            float a[8], b[8];
            #pragma unroll
            for (int i = 0; i < 4; i++){
                a[i]   = As[buf][kk][ty*4+i];
                a[4+i] = As[buf][kk][64+ty*4+i];
            }
            #pragma unroll
            for (int j = 0; j < 4; j++){
                b[j]   = Bs[buf][kk][tx*4+j];
                b[4+j] = Bs[buf][kk][64+tx*4+j];
            }
            #pragma unroll
            for (int i = 0; i < 8; i++)
                #pragma unroll
                for (int j = 0; j < 8; j++) acc[i][j] += a[i]*b[j];
        }
        buf ^= 1;
    }
    #pragma unroll
    for (int ih = 0; ih < 2; ih++){
        #pragma unroll
        for (int i = 0; i < 4; i++){
            int gr = rowBase + ih*64 + ty*4 + i;
            if (gr >= M) continue;
            if (mode == 6){
                int s = segidx[gr];
                float* mrow = atomMax + (size_t)s*Nn;
                float* srow = atomSum + (size_t)s*Nn;
                #pragma unroll
                for (int jh = 0; jh < 2; jh++){
                    int gc0 = colBase + jh*64 + tx*4;
                    size_t idx0 = (size_t)gr*Nn + gc0;
                    #pragma unroll
                    for (int j = 0; j < 4; j++){
                        float val = apply_epi(acc[ih*4+i][jh*4+j], 6, gr, idx0+j, gc0+j,
                                              bias, ls, add1, add2, maski);
                        atomicMaxF(&mrow[gc0+j], val);
                        atomicAdd(&srow[gc0+j], val);
                    }
                }
            } else {
                #pragma unroll
                for (int jh = 0; jh < 2; jh++){
                    int gc0 = colBase + jh*64 + tx*4;
                    size_t idx0 = (size_t)gr*Nn + gc0;
                    float4 v;
                    v.x = apply_epi(acc[ih*4+i][jh*4+0], mode, gr, idx0+0, gc0+0, bias, ls, add1, add2, maski);
                    v.y = apply_epi(acc[ih*4+i][jh*4+1], mode, gr, idx0+1, gc0+1, bias, ls, add1, add2, maski);
                    v.z = apply_epi(acc[ih*4+i][jh*4+2], mode, gr, idx0+2, gc0+2, bias, ls, add1, add2, maski);
                    v.w = apply_epi(acc[ih*4+i][jh*4+3], mode, gr, idx0+3, gc0+3, bias, ls, add1, add2, maski);
                    *(float4*)(Cm + idx0) = v;
                }
            }
        }
    }
}

// ---------------- small SGEMM (adapter-down, N=16) with bias+gelu ----------------
#define BM 64
#define BN 64
#define BK 16
__global__ void k_sgemm_small(const float* __restrict__ A, const float* __restrict__ B,
                        float* __restrict__ Cm, int M, int Nn, int K,
                        const float* __restrict__ bias, int dogelu){
    __shared__ float As[BK][BM];
    __shared__ float Bs[BK][BN];
    int tid = threadIdx.x;
    int tx = tid & 15, ty = tid >> 4;
    int rowBase = blockIdx.y*BM, colBase = blockIdx.x*BN;
    float acc[4][4] = {};
    for (int k0 = 0; k0 < K; k0 += BK){
        #pragma unroll
        for (int i = tid; i < BM*BK; i += 256){
            int r = i / BK, c = i % BK;
            int gr = rowBase + r, gc = k0 + c;
            As[c][r] = (gr < M && gc < K) ? A[(size_t)gr*K + gc] : 0.f;
        }
        #pragma unroll
        for (int i = tid; i < BK*BN; i += 256){
            int r = i / BN, c = i % BN;
            int gr = k0 + r, gc = colBase + c;
            Bs[r][c] = (gr < K && gc < Nn) ? B[(size_t)gr*Nn + gc] : 0.f;
        }
        __syncthreads();
        #pragma unroll
        for (int kk = 0; kk < BK; kk++){
            float a[4], b[4];
            #pragma unroll
            for (int i = 0; i < 4; i++) a[i] = As[kk][ty*4+i];
            #pragma unroll
            for (int j = 0; j < 4; j++) b[j] = Bs[kk][tx*4+j];
            #pragma unroll
            for (int i = 0; i < 4; i++)
                #pragma unroll
                for (int j = 0; j < 4; j++) acc[i][j] += a[i]*b[j];
        }
        __syncthreads();
    }
    #pragma unroll
    for (int i = 0; i < 4; i++){
        int gr = rowBase + ty*4 + i;
        if (gr >= M) continue;
        #pragma unroll
        for (int j = 0; j < 4; j++){
            int gc = colBase + tx*4 + j;
            if (gc < Nn){
                float v = acc[i][j];
                if (dogelu) v = geluf(v + bias[gc]);
                Cm[(size_t)gr*Nn + gc] = v;
            }
        }
    }
}

// ---------------- row stats (mean, rstd) over Cc columns ----------------
__global__ void k_rowstats(const float* __restrict__ in, float* __restrict__ rm,
                           float* __restrict__ rr){
    int row = blockIdx.x;
    int tid = threadIdx.x;
    const float* xr = in + (size_t)row*Cc;
    float s = 0.f, sq = 0.f;
    for (int c = tid; c < Cc; c += 128){ float v = xr[c]; s += v; sq += v*v; }
    __shared__ float rs[128], rq[128];
    rs[tid] = s; rq[tid] = sq; __syncthreads();
    for (int o = 64; o > 0; o >>= 1){
        if (tid < o){ rs[tid] += rs[tid+o]; rq[tid] += rq[tid+o]; }
        __syncthreads();
    }
    if (tid == 0){
        float m = rs[0]*(1.0f/Cc);
        float var = rq[0]*(1.0f/Cc) - m*m;
        rm[row] = m;
        rr[row] = rsqrtf(var + EPSv);
    }
}

// ---------------- extract feat + row stats + cluster pool atomics + count, one pass ----------------
__global__ void k_extract_stats(const float* __restrict__ x2, float* __restrict__ feat,
                                float* __restrict__ rm, float* __restrict__ rr,
                                const int* __restrict__ cluster,
                                float* __restrict__ smax, float* __restrict__ ssum,
                                int* __restrict__ scnt){
    int r = blockIdx.x;                    // 0..FROWS-1
    int tid = threadIdx.x;
    int b = r >> 9, g = r & 511;           // Gg = 512
    const float* src = x2 + ((size_t)(b*NN + 1 + g))*Cc;
    float* dst = feat + (size_t)r*Cc;
    int seg = cluster[r];
    float* mrow = smax + (size_t)seg*Cc;
    float* srow = ssum + (size_t)seg*Cc;
    float s = 0.f, sq = 0.f;
    for (int c = tid; c < Cc; c += 128){
        float v = src[c];
        dst[c] = v;
        atomicMaxF(&mrow[c], v);
        atomicAdd(&srow[c], v);
        s += v; sq += v*v;
    }
    if (tid == 0) atomicAdd(&scnt[seg], 1);
    __shared__ float rs[128], rq[128];
    rs[tid] = s; rq[tid] = sq; __syncthreads();
    for (int o = 64; o > 0; o >>= 1){
        if (tid < o){ rs[tid] += rs[tid+o]; rq[tid] += rq[tid+o]; }
        __syncthreads();
    }
    if (tid == 0){
        float m = rs[0]*(1.0f/Cc);
        float var = rq[0]*(1.0f/Cc) - m*m;
        rm[r] = m;
        rr[r] = rsqrtf(var + EPSv);
    }
}

// ---------------- pooled BatchNorm+GELU, coalesced (32ch x 8row threads) ----------------
// grid: (Cc/32, nviews); block: 256 threads. Batched over blockIdx.y.
__global__ __launch_bounds__(256) void k_bn_gelu_pool(
        const float* __restrict__ mx0, const float* __restrict__ sm0,
        const int* __restrict__ cnt0,
        const float* __restrict__ g0, const float* __restrict__ b0,
        float* __restrict__ out0, int rows){
    int v = blockIdx.y;
    const float* mx = mx0 + (size_t)v*rows*Cc;
    const float* sm = sm0 + (size_t)v*rows*Cc;
    const int* cnt = cnt0 + (size_t)v*rows;
    const float* g = g0 + (size_t)v*Cc;
    const float* b = b0 + (size_t)v*Cc;
    float* out = out0 + (size_t)v*rows*Cc;
    int cc = threadIdx.x & 31;             // channel lane within tile
    int rr = threadIdx.x >> 5;             // row lane 0..7
    int c = blockIdx.x*32 + cc;
    float s = 0.f, sq = 0.f;
    for (int r = rr; r < rows; r += 8){
        float m = mx[(size_t)r*Cc + c];
        if (isinf(m) && m < 0.f) m = 0.f;
        float vv = m + sm[(size_t)r*Cc + c]/fmaxf((float)cnt[r], 1.0f);
        s += vv; sq += vv*vv;
    }
    __shared__ float rs[8][32], rq[8][32];
    __shared__ float smean[32], srstd[32];
    rs[rr][cc] = s; rq[rr][cc] = sq;
    __syncthreads();
    if (rr == 0){
        #pragma unroll
        for (int k = 1; k < 8; k++){ s += rs[k][cc]; sq += rq[k][cc]; }
        float m0 = s/rows;
        float var = sq/rows - m0*m0;
        smean[cc] = m0;
        srstd[cc] = rsqrtf(var + EPSv);
    }
    __syncthreads();
    float m0 = smean[cc], rstd = srstd[cc];
    float gg = g[c], bb = b[c];
    for (int r = rr; r < rows; r += 8){
        float m = mx[(size_t)r*Cc + c];
        if (isinf(m) && m < 0.f) m = 0.f;
        float vv = m + sm[(size_t)r*Cc + c]/fmaxf((float)cnt[r], 1.0f);
        out[(size_t)r*Cc + c] = geluf((vv - m0)*rstd*gg + bb);
    }
}

// ---------------- attention: 8 queries per block ----------------
__global__ void k_attn(const float* __restrict__ qkv, float* __restrict__ out){
    int qb = blockIdx.x, h = blockIdx.y, b = blockIdx.z;
    int q0 = qb*8;
    int tid = threadIdx.x;
    __shared__ float qs[8][HD];
    __shared__ float sc[8][NN];
    __shared__ float red[128];
    __shared__ float inv[8];
    const float* base = qkv + (size_t)b*NN*C3;
    for (int i = tid; i < 8*HD; i += 128){
        int qi = i / HD, d = i % HD;
        int qrow = q0 + qi;
        qs[qi][d] = (qrow < NN) ? base[(size_t)qrow*C3 + h*HD + d] : 0.f;
    }
    __syncthreads();
    for (int m = tid; m < NN; m += 128){
        const float* kp = base + (size_t)m*C3 + Cc + h*HD;
        float a0=0,a1=0,a2=0,a3=0,a4=0,a5=0,a6=0,a7=0;
        #pragma unroll 8
        for (int d = 0; d < HD; d++){
            float kd = kp[d];
            a0 += qs[0][d]*kd; a1 += qs[1][d]*kd; a2 += qs[2][d]*kd; a3 += qs[3][d]*kd;
            a4 += qs[4][d]*kd; a5 += qs[5][d]*kd; a6 += qs[6][d]*kd; a7 += qs[7][d]*kd;
        }
        sc[0][m]=a0*0.125f; sc[1][m]=a1*0.125f; sc[2][m]=a2*0.125f; sc[3][m]=a3*0.125f;
        sc[4][m]=a4*0.125f; sc[5][m]=a5*0.125f; sc[6][m]=a6*0.125f; sc[7][m]=a7*0.125f;
    }
    __syncthreads();
    for (int qi = 0; qi < 8; qi++){
        float lm = -INFINITY;
        for (int m = tid; m < NN; m += 128) lm = fmaxf(lm, sc[qi][m]);
        red[tid] = lm; __syncthreads();
        for (int o = 64; o > 0; o >>= 1){ if (tid < o) red[tid] = fmaxf(red[tid], red[tid+o]); __syncthreads(); }
        float mx = red[0]; __syncthreads();
        float ls = 0.f;
        for (int m = tid; m < NN; m += 128){ float e = expf(sc[qi][m] - mx); sc[qi][m] = e; ls += e; }
        red[tid] = ls; __syncthreads();
        for (int o = 64; o > 0; o >>= 1){ if (tid < o) red[tid] += red[tid+o]; __syncthreads(); }
        if (tid == 0) inv[qi] = 1.0f/red[0];
        __syncthreads();
    }
    int d = tid & 63, half = tid >> 6;
    float acc[8] = {0,0,0,0,0,0,0,0};
    for (int m = half; m < NN; m += 2){
        float vv = base[(size_t)m*C3 + 2*Cc + h*HD + d];
        #pragma unroll
        for (int qi = 0; qi < 8; qi++) acc[qi] += sc[qi][m]*vv;
    }
    for (int qi = 0; qi < 8; qi++){
        red[tid] = acc[qi]; __syncthreads();
        if (half == 0 && (q0+qi) < NN)
            out[((size_t)b*NN + q0 + qi)*Cc + h*HD + d] = (red[tid] + red[tid+64])*inv[qi];
        __syncthreads();
    }
}

// ---------------- init / count kernels ----------------
__global__ void k_fill2(float* __restrict__ mx, float* __restrict__ sm, size_t n){
    size_t e = (size_t)blockIdx.x*256 + threadIdx.x;
    if (e < n){ mx[e] = -INFINITY; sm[e] = 0.f; }
}
__global__ void k_zeroi(int* __restrict__ p, int n){
    int e = blockIdx.x*256 + threadIdx.x;
    if (e < n) p[e] = 0;
}
__global__ void k_count_b(const int* __restrict__ idx0, int* __restrict__ cnt0,
                          int rows, int nseg){
    int v = blockIdx.y;
    const int* idx = idx0 + (size_t)v*rows;
    int* cnt = cnt0 + (size_t)v*nseg;
    int r = blockIdx.x*256 + threadIdx.x;
    if (r < rows) atomicAdd(&cnt[idx[r]], 1);
}

// ---------------- final: gather + cosine sims + weighted sum + output ----------------
__global__ void k_final(const float* __restrict__ x2, const float* __restrict__ d2all,
                        const int* __restrict__ fgi, const float* __restrict__ bn3d,
                        const int* __restrict__ cluster, float* __restrict__ out){
    int row = blockIdx.x;            // 0 .. ROWS-1
    int tid = threadIdx.x;
    int b = row / NN, n = row % NN;
    if (n == 0){
        for (int c = tid; c < Cc; c += 128) out[(size_t)row*Cc + c] = x2[(size_t)row*Cc + c];
        return;
    }
    int r = b*Gg + (n - 1);
    const float* x3 = bn3d + (size_t)cluster[r]*Cc;
    const float* sup[Vv];
    #pragma unroll
    for (int v = 0; v < Vv; v++)
        sup[v] = d2all + ((size_t)v*D2D + fgi[(size_t)v*FROWS + r])*Cc;
    float dot[Vv] = {}, nv[Vv] = {}, n3 = 0.f;
    for (int c = tid; c < Cc; c += 128){
        float a = x3[c]; n3 += a*a;
        #pragma unroll
        for (int v = 0; v < Vv; v++){
            float s = sup[v][c];
            dot[v] += s*a; nv[v] += s*s;
        }
    }
    __shared__ float sh[13][128];
    sh[0][tid] = n3;
    #pragma unroll
    for (int v = 0; v < Vv; v++){ sh[1+v][tid] = dot[v]; sh[7+v][tid] = nv[v]; }
    __syncthreads();
    for (int o = 64; o > 0; o >>= 1){
        if (tid < o)
            #pragma unroll
            for (int k = 0; k < 13; k++) sh[k][tid] += sh[k][tid+o];
        __syncthreads();
    }
    __shared__ float w[Vv];
    if (tid == 0){
        float n3v = fmaxf(sqrtf(sh[0][0]), 1e-8f);
        float ssum = 0.f, sv[Vv];
        #pragma unroll
        for (int v = 0; v < Vv; v++){
            float nvv = fmaxf(sqrtf(sh[7+v][0]), 1e-8f);
            float cs = sh[1+v][0]/(n3v*nvv);
            sv[v] = (cs + 1.0f)*0.5f;
            ssum += sv[v];
        }
        #pragma unroll
        for (int v = 0; v < Vv; v++) w[v] = sv[v]/ssum;
    }
    __syncthreads();
    for (int c = tid; c < Cc; c += 128){
        float acc = x2[(size_t)row*Cc + c];
        #pragma unroll
        for (int v = 0; v < Vv; v++) acc += w[v]*sup[v][c];
        out[(size_t)row*Cc + c] = acc;
    }
}

// ---------------- host ----------------
#define GRID1D(n) dim3((unsigned)(((n)+255)/256)), dim3(256)
#define NOEPI nullptr, nullptr, nullptr, nullptr, nullptr
#define NOLN  nullptr, nullptr, nullptr, nullptr, 0, 0, 0, 0, 0
#define NOSEG nullptr, nullptr, nullptr, 0

extern "C" void kernel_launch(void* const* d_in, const int* in_sizes, int n_in,
                              void* d_out, int out_size){
    const float *x, *ln1_g, *ln1_b, *qkv_w, *proj_w, *proj_b, *ls1_g, *ln2_g, *ln2_b;
    const float *fc1_w, *fc1_b, *fc2_w, *fc2_b, *ls2_g;
    const float *ad_down_w, *ad_down_b, *ad_up_w, *ad_up_b;
    const float *bn3d_g, *bn3d_b, *norm3_g, *norm3_b, *attn1_w, *attn1_b, *bn2d_g, *bn2d_b;
    const int *cluster, *fgi, *maskp;

    if (in_sizes[1] == FROWS){
        // setup_inputs dict order
        x=(const float*)d_in[0];
        cluster=(const int*)d_in[1]; fgi=(const int*)d_in[2]; maskp=(const int*)d_in[3];
        ln1_g=(const float*)d_in[4];  ln1_b=(const float*)d_in[5];  qkv_w=(const float*)d_in[6];
        proj_w=(const float*)d_in[7]; proj_b=(const float*)d_in[8]; ls1_g=(const float*)d_in[9];
        ln2_g=(const float*)d_in[10]; ln2_b=(const float*)d_in[11];
        fc1_w=(const float*)d_in[12]; fc1_b=(const float*)d_in[13];
        fc2_w=(const float*)d_in[14]; fc2_b=(const float*)d_in[15]; ls2_g=(const float*)d_in[16];
        ad_down_w=(const float*)d_in[17]; ad_down_b=(const float*)d_in[18];
        ad_up_w=(const float*)d_in[19];   ad_up_b=(const float*)d_in[20];
        bn3d_g=(const float*)d_in[21]; bn3d_b=(const float*)d_in[22];
        norm3_g=(const float*)d_in[23]; norm3_b=(const float*)d_in[24];
        attn1_w=(const float*)d_in[25]; attn1_b=(const float*)d_in[26];
        bn2d_g=(const float*)d_in[27];  bn2d_b=(const float*)d_in[28];
    } else {
        // reference signature order
        x=(const float*)d_in[0];
        ln1_g=(const float*)d_in[1];  ln1_b=(const float*)d_in[2];  qkv_w=(const float*)d_in[3];
        proj_w=(const float*)d_in[4]; proj_b=(const float*)d_in[5]; ls1_g=(const float*)d_in[6];
        ln2_g=(const float*)d_in[7];  ln2_b=(const float*)d_in[8];
        fc1_w=(const float*)d_in[9];  fc1_b=(const float*)d_in[10];
        fc2_w=(const float*)d_in[11]; fc2_b=(const float*)d_in[12]; ls2_g=(const float*)d_in[13];
        ad_down_w=(const float*)d_in[14]; ad_down_b=(const float*)d_in[15];
        ad_up_w=(const float*)d_in[16];   ad_up_b=(const float*)d_in[17];
        bn3d_g=(const float*)d_in[18]; bn3d_b=(const float*)d_in[19];
        norm3_g=(const float*)d_in[20]; norm3_b=(const float*)d_in[21];
        attn1_w=(const float*)d_in[22]; attn1_b=(const float*)d_in[23];
        bn2d_g=(const float*)d_in[24];  bn2d_b=(const float*)d_in[25];
        cluster=(const int*)d_in[26]; fgi=(const int*)d_in[27]; maskp=(const int*)d_in[28];
    }

    float *p_qkv, *p_att, *p_x1, *p_h, *p_xffn, *p_adh, *p_x2, *p_feat;
    float *p_rm, *p_rr, *p_rmF, *p_rrF;
    float *p_segmax, *p_segsum, *p_bn3d;
    float *p_gmax, *p_gsum, *p_d2;
    int *p_segcnt, *p_gcnt;
    cudaGetSymbolAddress((void**)&p_qkv, g_qkv);
    cudaGetSymbolAddress((void**)&p_att, g_att);
    cudaGetSymbolAddress((void**)&p_x1, g_x1);
    cudaGetSymbolAddress((void**)&p_h, g_h);
    cudaGetSymbolAddress((void**)&p_xffn, g_xffn);
    cudaGetSymbolAddress((void**)&p_adh, g_adh);
    cudaGetSymbolAddress((void**)&p_x2, g_x2);
    cudaGetSymbolAddress((void**)&p_feat, g_feat);
    cudaGetSymbolAddress((void**)&p_rm, g_rm);
    cudaGetSymbolAddress((void**)&p_rr, g_rr);
    cudaGetSymbolAddress((void**)&p_rmF, g_rmF);
    cudaGetSymbolAddress((void**)&p_rrF, g_rrF);
    cudaGetSymbolAddress((void**)&p_segmax, g_segmax);
    cudaGetSymbolAddress((void**)&p_segsum, g_segsum);
    cudaGetSymbolAddress((void**)&p_segcnt, g_segcnt);
    cudaGetSymbolAddress((void**)&p_bn3d, g_bn3d);
    cudaGetSymbolAddress((void**)&p_gmax, g_gmax);
    cudaGetSymbolAddress((void**)&p_gsum, g_gsum);
    cudaGetSymbolAddress((void**)&p_gcnt, g_gcnt);
    cudaGetSymbolAddress((void**)&p_d2, g_d2);
    float* out = (float*)d_out;

    // ---- 0. init pooling buffers ----
    k_fill2<<<GRID1D((size_t)NCLUST*Cc)>>>(p_segmax, p_segsum, (size_t)NCLUST*Cc);
    k_zeroi<<<GRID1D(NCLUST)>>>(p_segcnt, NCLUST);
    k_fill2<<<GRID1D((size_t)Vv*D2D*Cc)>>>(p_gmax, p_gsum, (size_t)Vv*D2D*Cc);
    k_zeroi<<<GRID1D(Vv*D2D)>>>(p_gcnt, Vv*D2D);
    k_count_b<<<dim3((FROWS+255)/256, Vv), 256>>>(fgi, p_gcnt, FROWS, D2D);

    // ---- 1. LN1-stats + fused QKV GEMM + attention + proj(+residual) ----
    k_rowstats<<<ROWS, 128>>>(x, p_rm, p_rr);
    k_sgemm_big<<<dim3(C3/TBN, (ROWS+TBM-1)/TBM, 1), 256>>>(
        x, qkv_w, p_qkv, ROWS, C3, Cc,
        0, NOEPI, p_rm, p_rr, ln1_g, ln1_b, 0, 0, 0, 0, 0, NOSEG);
    k_attn<<<dim3((NN+7)/8, Hh, Bb), 128>>>(p_qkv, p_att);
    k_sgemm_big<<<dim3(Cc/TBN, (ROWS+TBM-1)/TBM, 1), 256>>>(
        p_att, proj_w, p_x1, ROWS, Cc, Cc,
        2, proj_b, ls1_g, x, nullptr, nullptr, NOLN, NOSEG);

    // ---- 2. LN2-stats + fused fc1 + fc2 + adapter ----
    k_rowstats<<<ROWS, 128>>>(p_x1, p_rm, p_rr);
    k_sgemm_big<<<dim3(C4/TBN, (ROWS+TBM-1)/TBM, 1), 256>>>(
        p_x1, fc1_w, p_h, ROWS, C4, Cc,
        1, fc1_b, nullptr, nullptr, nullptr, nullptr,
        p_rm, p_rr, ln2_g, ln2_b, 0, 0, 0, 0, 0, NOSEG);
    k_sgemm_big<<<dim3(Cc/TBN, (ROWS+TBM-1)/TBM, 1), 256>>>(
        p_h, fc2_w, p_xffn, ROWS, Cc, C4,
        3, fc2_b, ls2_g, nullptr, nullptr, nullptr, NOLN, NOSEG);
    k_sgemm_small<<<dim3(1, (ROWS+63)/64), 256>>>(p_xffn, ad_down_w, p_adh, ROWS, 16, Cc,
                                                  ad_down_b, 1);
    k_sgemm_big<<<dim3(Cc/TBN, (ROWS+TBM-1)/TBM, 1), 256>>>(
        p_adh, ad_up_w, p_x2, ROWS, Cc, 16,
        4, ad_up_b, nullptr, p_x1, p_xffn, nullptr, NOLN, NOSEG);

    // ---- 3. feat extraction + stats + cluster pooling in one pass, then bn_gelu ----
    k_extract_stats<<<FROWS, 128>>>(p_x2, p_feat, p_rmF, p_rrF,
                                    cluster, p_segmax, p_segsum, p_segcnt);
    k_bn_gelu_pool<<<dim3(Cc/32, 1), 256>>>(p_segmax, p_segsum, p_segcnt, bn3d_g, bn3d_b,
                                            p_bn3d, NCLUST);

    // ---- 4. view branches: one batched GEMM with LN prologue + pooled-atomic epilogue ----
    k_sgemm_big<<<dim3(Cc/TBN, FROWS/TBM, Vv), 256>>>(
        p_feat, attn1_w, nullptr, FROWS, Cc, Cc,
        6, attn1_b, nullptr, p_feat, nullptr, maskp,
        p_rmF, p_rrF, norm3_g, norm3_b,
        (long)Cc*Cc, 0L, Cc, Cc, FROWS,
        fgi, p_gmax, p_gsum, D2D);
    k_bn_gelu_pool<<<dim3(Cc/32, Vv), 256>>>(p_gmax, p_gsum, p_gcnt, bn2d_g, bn2d_b,
                                             p_d2, D2D);

    // ---- 5. gather + sims + weighted combine + output ----
    k_final<<<ROWS, 128>>>(p_x2, p_d2, fgi, p_bn3d, cluster, out);
}